// round 2
// baseline (speedup 1.0000x reference)
#include <cuda_runtime.h>
#include <math.h>

// Shapes (fixed): x = (4,8,8192,128) fp32
#define NBH     32
#define SLEN    8192
#define DIMC    128
#define NREG    96
#define NOUTC   32
#define TPB     128
#define NCHUNK  64
#define CHUNK_S 128   // SLEN / NCHUNK

// static device scratch (no runtime allocation)
__device__ float g_partial[NBH * NCHUNK * DIMC];
__device__ int   g_order[NBH * DIMC];

// ---------------------------------------------------------------------------
// Stage A: partial channel sum-of-squares (coalesced)
// ---------------------------------------------------------------------------
__global__ void __launch_bounds__(DIMC) k_chnorm(const float* __restrict__ x)
{
    int bh = blockIdx.y, ck = blockIdx.x, c = threadIdx.x;
    const float* p = x + ((size_t)bh * SLEN + (size_t)ck * CHUNK_S) * DIMC + c;
    float acc = 0.f;
#pragma unroll 8
    for (int s = 0; s < CHUNK_S; ++s) {
        float t = p[(size_t)s * DIMC];
        acc = fmaf(t, t, acc);
    }
    g_partial[(bh * NCHUNK + ck) * DIMC + c] = acc;
}

// ---------------------------------------------------------------------------
// Stage B: reduce + top-32 membership + stable order (non-outliers first)
// ---------------------------------------------------------------------------
__global__ void __launch_bounds__(DIMC) k_order()
{
    __shared__ float nsq[DIMC];
    __shared__ int   flag[DIMC];
    int bh = blockIdx.x, c = threadIdx.x;
    float a = 0.f;
    for (int k = 0; k < NCHUNK; ++k) a += g_partial[(bh * NCHUNK + k) * DIMC + c];
    nsq[c] = a;
    __syncthreads();
    int rank = 0;
    for (int d = 0; d < DIMC; ++d) {
        float nd = nsq[d];
        rank += (nd > a) || (nd == a && d < c);   // top_k ties: lower index wins
    }
    int isout = (rank < NOUTC) ? 1 : 0;
    flag[c] = isout;
    __syncthreads();
    int pos = 0;
    for (int d = 0; d < c; ++d) pos += (flag[d] == isout);
    g_order[bh * DIMC + (isout ? (NREG + pos) : pos)] = c;
}

// ---------------------------------------------------------------------------
// helpers
// ---------------------------------------------------------------------------
__device__ __forceinline__ float dot4(float4 m, float v0, float v1, float v2, float v3, float a)
{
    return fmaf(m.x, v0, fmaf(m.y, v1, fmaf(m.z, v2, fmaf(m.w, v3, a))));
}
__device__ __forceinline__ void fma4(float4& A, float s, float4 m)
{
    A.x = fmaf(s, m.x, A.x);
    A.y = fmaf(s, m.y, A.y);
    A.z = fmaf(s, m.z, A.z);
    A.w = fmaf(s, m.w, A.w);
}
__device__ __forceinline__ float comp(const float4& A, int u)  // u compile-time
{
    return (u == 0) ? A.x : ((u == 1) ? A.y : ((u == 2) ? A.z : A.w));
}

// ---------------------------------------------------------------------------
// Stage C: fused roundtrip, one row per thread
// ---------------------------------------------------------------------------
__global__ void __launch_bounds__(TPB, 2) k_main(
    const float* __restrict__ x,
    const float* __restrict__ rotR, const float* __restrict__ rotO,
    const float* __restrict__ cbR,  const float* __restrict__ cbO,
    const float* __restrict__ SR,   const float* __restrict__ SO,
    float* __restrict__ out)
{
    __shared__ __align__(16) float shM[NREG * NREG];     // rotR, later SR
    __shared__ __align__(16) float shRo[NOUTC * NOUTC];
    __shared__ __align__(16) float shSo[NOUTC * NOUTC];
    __shared__ int shOrd[DIMC];

    const int bh = blockIdx.y;
    for (int i = threadIdx.x; i < NREG * NREG; i += TPB) shM[i] = rotR[i];
    for (int i = threadIdx.x; i < NOUTC * NOUTC; i += TPB) { shRo[i] = rotO[i]; shSo[i] = SO[i]; }
    if (threadIdx.x < DIMC) shOrd[threadIdx.x] = g_order[bh * DIMC + threadIdx.x];
    __syncthreads();

    const size_t row = (size_t)bh * SLEN + (size_t)blockIdx.x * TPB + threadIdx.x;
    const float* xr   = x   + row * DIMC;
    float*       orow = out + row * DIMC;

    const float cR0 = __ldg(cbR), cR1 = __ldg(cbR + 1);
    const float midR = 0.5f * (cR0 + cR1);
    const float cO0 = __ldg(cbO), cO1 = __ldg(cbO + 1), cO2 = __ldg(cbO + 2), cO3 = __ldg(cbO + 3);
    const float mO0 = 0.5f * (cO0 + cO1), mO1 = 0.5f * (cO1 + cO2), mO2 = 0.5f * (cO2 + cO3);
    const float SCALE_R = 1.2533141373155003f / 96.0f;   // sqrt(pi/2)/96
    const float SCALE_O = 1.2533141373155003f / 32.0f;   // sqrt(pi/2)/32

    // ---------------- gather regular subspace ----------------
    float v[NREG];
    float nsq = 0.f;
#pragma unroll
    for (int j = 0; j < NREG; ++j) {
        float t = __ldg(xr + shOrd[j]);
        v[j] = t;
        nsq = fmaf(t, t, nsq);
    }
    float nrm = fmaxf(sqrtf(nsq), 1e-8f);
    float inv = 1.0f / nrm;

    // ---------------- REG pass 1: y = (xp/n) @ rot.T -> 1-bit codes ----------------
    unsigned sb0 = 0u, sb1 = 0u, sb2 = 0u;
#pragma unroll 1
    for (int ig = 0; ig < 24; ++ig) {
        const float4* r0 = (const float4*)(shM + (4 * ig + 0) * NREG);
        const float4* r1 = (const float4*)(shM + (4 * ig + 1) * NREG);
        const float4* r2 = (const float4*)(shM + (4 * ig + 2) * NREG);
        const float4* r3 = (const float4*)(shM + (4 * ig + 3) * NREG);
        float a0 = 0.f, a1 = 0.f, a2 = 0.f, a3 = 0.f;
#pragma unroll
        for (int q = 0; q < 24; ++q) {
            float v0 = v[4*q], v1 = v[4*q+1], v2 = v[4*q+2], v3 = v[4*q+3];
            a0 = dot4(r0[q], v0, v1, v2, v3, a0);
            a1 = dot4(r1[q], v0, v1, v2, v3, a1);
            a2 = dot4(r2[q], v0, v1, v2, v3, a2);
            a3 = dot4(r3[q], v0, v1, v2, v3, a3);
        }
        unsigned b =  (unsigned)(a0 * inv > midR)
                   | ((unsigned)(a1 * inv > midR) << 1)
                   | ((unsigned)(a2 * inv > midR) << 2)
                   | ((unsigned)(a3 * inv > midR) << 3);
        if      (ig < 8)  sb0 |= b << (ig * 4);
        else if (ig < 16) sb1 |= b << ((ig - 8) * 4);
        else              sb2 |= b << ((ig - 16) * 4);
    }

    // ---------------- REG pass 2: x_mse = (yhat@rot)*n ; stash; r = xp - x_mse ----
    float rsq = 0.f;
#pragma unroll
    for (int jg = 0; jg < NREG; jg += 16) {
        float4 A[4];
        A[0] = make_float4(0.f, 0.f, 0.f, 0.f);
        A[1] = A[0]; A[2] = A[0]; A[3] = A[0];
#pragma unroll 1
        for (int i = 0; i < NREG; ++i) {
            unsigned w = (i < 32) ? sb0 : ((i < 64) ? sb1 : sb2);
            float yh = ((w >> (i & 31)) & 1u) ? cR1 : cR0;
            const float4* mp = (const float4*)(shM + i * NREG + jg);
            fma4(A[0], yh, mp[0]);
            fma4(A[1], yh, mp[1]);
            fma4(A[2], yh, mp[2]);
            fma4(A[3], yh, mp[3]);
        }
#pragma unroll
        for (int u = 0; u < 16; ++u) {
            int j = jg + u;
            float xm = comp(A[u >> 2], u & 3) * nrm;
            orow[shOrd[j]] = xm;          // stash x_mse (re-read by this thread)
            float r = v[j] - xm;
            v[j] = r;
            rsq = fmaf(r, r, rsq);
        }
    }
    float rn = fmaxf(sqrtf(rsq), 1e-10f);

    // reload shM with S_reg
    __syncthreads();
    for (int i = threadIdx.x; i < NREG * NREG; i += TPB) shM[i] = SR[i];
    __syncthreads();

    // ---------------- REG pass 3: sign(S @ r) ----------------
    unsigned gb0 = 0u, gb1 = 0u, gb2 = 0u;
#pragma unroll 1
    for (int ig = 0; ig < 24; ++ig) {
        const float4* r0 = (const float4*)(shM + (4 * ig + 0) * NREG);
        const float4* r1 = (const float4*)(shM + (4 * ig + 1) * NREG);
        const float4* r2 = (const float4*)(shM + (4 * ig + 2) * NREG);
        const float4* r3 = (const float4*)(shM + (4 * ig + 3) * NREG);
        float a0 = 0.f, a1 = 0.f, a2 = 0.f, a3 = 0.f;
#pragma unroll
        for (int q = 0; q < 24; ++q) {
            float v0 = v[4*q], v1 = v[4*q+1], v2 = v[4*q+2], v3 = v[4*q+3];
            a0 = dot4(r0[q], v0, v1, v2, v3, a0);
            a1 = dot4(r1[q], v0, v1, v2, v3, a1);
            a2 = dot4(r2[q], v0, v1, v2, v3, a2);
            a3 = dot4(r3[q], v0, v1, v2, v3, a3);
        }
        unsigned b =  (unsigned)(a0 >= 0.f)
                   | ((unsigned)(a1 >= 0.f) << 1)
                   | ((unsigned)(a2 >= 0.f) << 2)
                   | ((unsigned)(a3 >= 0.f) << 3);
        if      (ig < 8)  gb0 |= b << (ig * 4);
        else if (ig < 16) gb1 |= b << ((ig - 8) * 4);
        else              gb2 |= b << ((ig - 16) * 4);
    }

    // ---------------- REG pass 4: out = x_mse + scale*(signs@S)*rn ----------------
    {
        float cc = SCALE_R * rn;
#pragma unroll
        for (int jg = 0; jg < NREG; jg += 16) {
            int   oix[16];
            float xmv[16];
#pragma unroll
            for (int u = 0; u < 16; ++u) { oix[u] = shOrd[jg + u]; xmv[u] = orow[oix[u]]; }
            float4 A[4];
            A[0] = make_float4(0.f, 0.f, 0.f, 0.f);
            A[1] = A[0]; A[2] = A[0]; A[3] = A[0];
#pragma unroll 1
            for (int i = 0; i < NREG; ++i) {
                unsigned w = (i < 32) ? gb0 : ((i < 64) ? gb1 : gb2);
                float s = ((w >> (i & 31)) & 1u) ? 1.0f : -1.0f;
                const float4* mp = (const float4*)(shM + i * NREG + jg);
                fma4(A[0], s, mp[0]);
                fma4(A[1], s, mp[1]);
                fma4(A[2], s, mp[2]);
                fma4(A[3], s, mp[3]);
            }
#pragma unroll
            for (int u = 0; u < 16; ++u) {
                float sj = comp(A[u >> 2], u & 3);
                orow[oix[u]] = fmaf(cc, sj, xmv[u]);
            }
        }
    }

    // =====================  OUTLIER subspace (32 dims, 2-bit)  =====================
    float vo[NOUTC];
    float nsqo = 0.f;
#pragma unroll
    for (int j = 0; j < NOUTC; ++j) {
        float t = __ldg(xr + shOrd[NREG + j]);
        vo[j] = t;
        nsqo = fmaf(t, t, nsqo);
    }
    float nrmo = fmaxf(sqrtf(nsqo), 1e-8f);
    float invo = 1.0f / nrmo;

    // pass 1: 2-bit codes
    unsigned code0 = 0u, code1 = 0u;   // 2 bits per i, 16 codes per word
#pragma unroll 1
    for (int ig = 0; ig < 8; ++ig) {
        const float4* r0 = (const float4*)(shRo + (4 * ig + 0) * NOUTC);
        const float4* r1 = (const float4*)(shRo + (4 * ig + 1) * NOUTC);
        const float4* r2 = (const float4*)(shRo + (4 * ig + 2) * NOUTC);
        const float4* r3 = (const float4*)(shRo + (4 * ig + 3) * NOUTC);
        float a0 = 0.f, a1 = 0.f, a2 = 0.f, a3 = 0.f;
#pragma unroll
        for (int q = 0; q < 8; ++q) {
            float v0 = vo[4*q], v1 = vo[4*q+1], v2 = vo[4*q+2], v3 = vo[4*q+3];
            a0 = dot4(r0[q], v0, v1, v2, v3, a0);
            a1 = dot4(r1[q], v0, v1, v2, v3, a1);
            a2 = dot4(r2[q], v0, v1, v2, v3, a2);
            a3 = dot4(r3[q], v0, v1, v2, v3, a3);
        }
        float y0 = a0 * invo, y1 = a1 * invo, y2 = a2 * invo, y3 = a3 * invo;
        unsigned i0 = (unsigned)(y0 > mO0) + (unsigned)(y0 > mO1) + (unsigned)(y0 > mO2);
        unsigned i1 = (unsigned)(y1 > mO0) + (unsigned)(y1 > mO1) + (unsigned)(y1 > mO2);
        unsigned i2 = (unsigned)(y2 > mO0) + (unsigned)(y2 > mO1) + (unsigned)(y2 > mO2);
        unsigned i3 = (unsigned)(y3 > mO0) + (unsigned)(y3 > mO1) + (unsigned)(y3 > mO2);
        unsigned b8 = i0 | (i1 << 2) | (i2 << 4) | (i3 << 6);
        if (ig < 4) code0 |= b8 << (ig * 8);
        else        code1 |= b8 << ((ig - 4) * 8);
    }

    // pass 2: x_mse (kept in regs), r in vo
    float xmo[NOUTC];
    float rsqo = 0.f;
#pragma unroll
    for (int jg = 0; jg < NOUTC; jg += 16) {
        float4 A[4];
        A[0] = make_float4(0.f, 0.f, 0.f, 0.f);
        A[1] = A[0]; A[2] = A[0]; A[3] = A[0];
#pragma unroll 1
        for (int i = 0; i < NOUTC; ++i) {
            unsigned w = (i < 16) ? code0 : code1;
            unsigned idx = (w >> ((i & 15) * 2)) & 3u;
            float lo = (idx & 1u) ? cO1 : cO0;
            float hi = (idx & 1u) ? cO3 : cO2;
            float yh = (idx & 2u) ? hi : lo;
            const float4* mp = (const float4*)(shRo + i * NOUTC + jg);
            fma4(A[0], yh, mp[0]);
            fma4(A[1], yh, mp[1]);
            fma4(A[2], yh, mp[2]);
            fma4(A[3], yh, mp[3]);
        }
#pragma unroll
        for (int u = 0; u < 16; ++u) {
            int j = jg + u;
            float xm = comp(A[u >> 2], u & 3) * nrmo;
            xmo[j] = xm;
            float r = vo[j] - xm;
            vo[j] = r;
            rsqo = fmaf(r, r, rsqo);
        }
    }
    float rno = fmaxf(sqrtf(rsqo), 1e-10f);

    // pass 3: sign(S_out @ r)
    unsigned gbo = 0u;
#pragma unroll 1
    for (int ig = 0; ig < 8; ++ig) {
        const float4* r0 = (const float4*)(shSo + (4 * ig + 0) * NOUTC);
        const float4* r1 = (const float4*)(shSo + (4 * ig + 1) * NOUTC);
        const float4* r2 = (const float4*)(shSo + (4 * ig + 2) * NOUTC);
        const float4* r3 = (const float4*)(shSo + (4 * ig + 3) * NOUTC);
        float a0 = 0.f, a1 = 0.f, a2 = 0.f, a3 = 0.f;
#pragma unroll
        for (int q = 0; q < 8; ++q) {
            float v0 = vo[4*q], v1 = vo[4*q+1], v2 = vo[4*q+2], v3 = vo[4*q+3];
            a0 = dot4(r0[q], v0, v1, v2, v3, a0);
            a1 = dot4(r1[q], v0, v1, v2, v3, a1);
            a2 = dot4(r2[q], v0, v1, v2, v3, a2);
            a3 = dot4(r3[q], v0, v1, v2, v3, a3);
        }
        unsigned b =  (unsigned)(a0 >= 0.f)
                   | ((unsigned)(a1 >= 0.f) << 1)
                   | ((unsigned)(a2 >= 0.f) << 2)
                   | ((unsigned)(a3 >= 0.f) << 3);
        gbo |= b << (ig * 4);
    }

    // pass 4: out = x_mse + scale*(signs@S_out)*rn
    {
        float cc = SCALE_O * rno;
#pragma unroll
        for (int jg = 0; jg < NOUTC; jg += 16) {
            float4 A[4];
            A[0] = make_float4(0.f, 0.f, 0.f, 0.f);
            A[1] = A[0]; A[2] = A[0]; A[3] = A[0];
#pragma unroll 1
            for (int i = 0; i < NOUTC; ++i) {
                float s = ((gbo >> i) & 1u) ? 1.0f : -1.0f;
                const float4* mp = (const float4*)(shSo + i * NOUTC + jg);
                fma4(A[0], s, mp[0]);
                fma4(A[1], s, mp[1]);
                fma4(A[2], s, mp[2]);
                fma4(A[3], s, mp[3]);
            }
#pragma unroll
            for (int u = 0; u < 16; ++u) {
                int j = jg + u;
                float sj = comp(A[u >> 2], u & 3);
                orow[shOrd[NREG + j]] = fmaf(cc, sj, xmo[j]);
            }
        }
    }
}

// ---------------------------------------------------------------------------
extern "C" void kernel_launch(void* const* d_in, const int* in_sizes, int n_in,
                              void* d_out, int out_size)
{
    const float* x    = (const float*)d_in[0];
    const float* rotR = (const float*)d_in[1];
    const float* rotO = (const float*)d_in[2];
    const float* cbR  = (const float*)d_in[3];
    const float* cbO  = (const float*)d_in[4];
    const float* SR   = (const float*)d_in[5];
    const float* SO   = (const float*)d_in[6];
    float* out = (float*)d_out;

    dim3 gA(NCHUNK, NBH);
    k_chnorm<<<gA, DIMC>>>(x);
    k_order<<<NBH, DIMC>>>();
    dim3 gM(SLEN / TPB, NBH);
    k_main<<<gM, TPB>>>(x, rotR, rotO, cbR, cbO, SR, SO, out);
}

// round 3
// speedup vs baseline: 1.0458x; 1.0458x over previous
#include <cuda_runtime.h>
#include <math.h>

// Shapes (fixed): x = (4,8,8192,128) fp32
#define NBH     32
#define SLEN    8192
#define DIMC    128
#define NREG    96
#define NOUTC   32
#define TPB     128
#define NCHUNK  64
#define CHUNK_S 128   // SLEN / NCHUNK

typedef unsigned long long ull;

// static device scratch (no runtime allocation)
__device__ float g_partial[NBH * NCHUNK * DIMC];
__device__ int   g_order[NBH * DIMC];

// ---------------------------------------------------------------------------
// packed f32x2 helpers (FFMA2 path on sm_103a)
// ---------------------------------------------------------------------------
__device__ __forceinline__ ull pack2(float lo, float hi)
{
    ull r;
    asm("mov.b64 %0, {%1, %2};" : "=l"(r) : "f"(lo), "f"(hi));
    return r;
}
__device__ __forceinline__ void unpack2(ull p, float& lo, float& hi)
{
    asm("mov.b64 {%0, %1}, %2;" : "=f"(lo), "=f"(hi) : "l"(p));
}
__device__ __forceinline__ ull fma2(ull a, ull b, ull c)
{
    ull d;
    asm("fma.rn.f32x2 %0, %1, %2, %3;" : "=l"(d) : "l"(a), "l"(b), "l"(c));
    return d;
}
__device__ __forceinline__ ull mul2(ull a, ull b)
{
    ull d;
    asm("mul.rn.f32x2 %0, %1, %2;" : "=l"(d) : "l"(a), "l"(b));
    return d;
}

// ---------------------------------------------------------------------------
// Stage A: partial channel sum-of-squares (coalesced)
// ---------------------------------------------------------------------------
__global__ void __launch_bounds__(DIMC) k_chnorm(const float* __restrict__ x)
{
    int bh = blockIdx.y, ck = blockIdx.x, c = threadIdx.x;
    const float* p = x + ((size_t)bh * SLEN + (size_t)ck * CHUNK_S) * DIMC + c;
    float acc = 0.f;
#pragma unroll 8
    for (int s = 0; s < CHUNK_S; ++s) {
        float t = p[(size_t)s * DIMC];
        acc = fmaf(t, t, acc);
    }
    g_partial[(bh * NCHUNK + ck) * DIMC + c] = acc;
}

// ---------------------------------------------------------------------------
// Stage B: reduce + top-32 membership + stable order (non-outliers first)
// ---------------------------------------------------------------------------
__global__ void __launch_bounds__(DIMC) k_order()
{
    __shared__ float nsq[DIMC];
    __shared__ int   flag[DIMC];
    int bh = blockIdx.x, c = threadIdx.x;
    float a = 0.f;
    for (int k = 0; k < NCHUNK; ++k) a += g_partial[(bh * NCHUNK + k) * DIMC + c];
    nsq[c] = a;
    __syncthreads();
    int rank = 0;
    for (int d = 0; d < DIMC; ++d) {
        float nd = nsq[d];
        rank += (nd > a) || (nd == a && d < c);   // top_k ties: lower index wins
    }
    int isout = (rank < NOUTC) ? 1 : 0;
    flag[c] = isout;
    __syncthreads();
    int pos = 0;
    for (int d = 0; d < c; ++d) pos += (flag[d] == isout);
    g_order[bh * DIMC + (isout ? (NREG + pos) : pos)] = c;
}

// ---------------------------------------------------------------------------
// Stage C: fused roundtrip, one row per thread, packed f32x2 math
// ---------------------------------------------------------------------------
__global__ void __launch_bounds__(TPB, 2) k_main(
    const float* __restrict__ x,
    const float* __restrict__ rotR, const float* __restrict__ rotO,
    const float* __restrict__ cbR,  const float* __restrict__ cbO,
    const float* __restrict__ SR,   const float* __restrict__ SO,
    float* __restrict__ out)
{
    __shared__ __align__(16) float shM[NREG * NREG];     // rotR, later SR
    __shared__ __align__(16) float shRo[NOUTC * NOUTC];
    __shared__ __align__(16) float shSo[NOUTC * NOUTC];
    __shared__ int shOrd[DIMC];

    const int bh = blockIdx.y;
    for (int i = threadIdx.x; i < NREG * NREG; i += TPB) shM[i] = rotR[i];
    for (int i = threadIdx.x; i < NOUTC * NOUTC; i += TPB) { shRo[i] = rotO[i]; shSo[i] = SO[i]; }
    if (threadIdx.x < DIMC) shOrd[threadIdx.x] = g_order[bh * DIMC + threadIdx.x];
    __syncthreads();

    const size_t row = (size_t)bh * SLEN + (size_t)blockIdx.x * TPB + threadIdx.x;
    const float* xr   = x   + row * DIMC;
    float*       orow = out + row * DIMC;

    const float cR0 = __ldg(cbR), cR1 = __ldg(cbR + 1);
    const float midR = 0.5f * (cR0 + cR1);
    const float cO0 = __ldg(cbO), cO1 = __ldg(cbO + 1), cO2 = __ldg(cbO + 2), cO3 = __ldg(cbO + 3);
    const float mO0 = 0.5f * (cO0 + cO1), mO1 = 0.5f * (cO1 + cO2), mO2 = 0.5f * (cO2 + cO3);
    const float SCALE_R = 1.2533141373155003f / 96.0f;   // sqrt(pi/2)/96
    const float SCALE_O = 1.2533141373155003f / 32.0f;   // sqrt(pi/2)/32

    const ull cR0p    = pack2(cR0, cR0);
    const ull cR1p    = pack2(cR1, cR1);
    const ull onep    = pack2(1.f, 1.f);
    const ull negonep = pack2(-1.f, -1.f);

    // ---------------- gather regular subspace (packed) ----------------
    ull vp[NREG / 2];
    ull nsq2 = 0ull;
#pragma unroll
    for (int p = 0; p < NREG / 2; ++p) {
        float a = __ldg(xr + shOrd[2 * p]);
        float b = __ldg(xr + shOrd[2 * p + 1]);
        ull t = pack2(a, b);
        vp[p] = t;
        nsq2 = fma2(t, t, nsq2);
    }
    float nl, nh;
    unpack2(nsq2, nl, nh);
    float nrm = fmaxf(sqrtf(nl + nh), 1e-8f);
    float inv = 1.0f / nrm;
    const ull nrmp = pack2(nrm, nrm);

    // ---------------- REG pass 1: y = (xp/n) @ rot.T -> 1-bit codes ----------------
    unsigned sb0 = 0u, sb1 = 0u, sb2 = 0u;
#pragma unroll 1
    for (int ig = 0; ig < 24; ++ig) {
        const ulonglong2* r0 = (const ulonglong2*)(shM + (4 * ig + 0) * NREG);
        const ulonglong2* r1 = (const ulonglong2*)(shM + (4 * ig + 1) * NREG);
        const ulonglong2* r2 = (const ulonglong2*)(shM + (4 * ig + 2) * NREG);
        const ulonglong2* r3 = (const ulonglong2*)(shM + (4 * ig + 3) * NREG);
        ull a0 = 0ull, a1 = 0ull, a2 = 0ull, a3 = 0ull;
#pragma unroll
        for (int q = 0; q < 24; ++q) {
            ull v0 = vp[2 * q], v1 = vp[2 * q + 1];
            ulonglong2 m0 = r0[q]; a0 = fma2(m0.x, v0, a0); a0 = fma2(m0.y, v1, a0);
            ulonglong2 m1 = r1[q]; a1 = fma2(m1.x, v0, a1); a1 = fma2(m1.y, v1, a1);
            ulonglong2 m2 = r2[q]; a2 = fma2(m2.x, v0, a2); a2 = fma2(m2.y, v1, a2);
            ulonglong2 m3 = r3[q]; a3 = fma2(m3.x, v0, a3); a3 = fma2(m3.y, v1, a3);
        }
        float l0, h0, l1, h1, l2, h2, l3, h3;
        unpack2(a0, l0, h0); unpack2(a1, l1, h1);
        unpack2(a2, l2, h2); unpack2(a3, l3, h3);
        unsigned b =  (unsigned)((l0 + h0) * inv > midR)
                   | ((unsigned)((l1 + h1) * inv > midR) << 1)
                   | ((unsigned)((l2 + h2) * inv > midR) << 2)
                   | ((unsigned)((l3 + h3) * inv > midR) << 3);
        if      (ig < 8)  sb0 |= b << (ig * 4);
        else if (ig < 16) sb1 |= b << ((ig - 8) * 4);
        else              sb2 |= b << ((ig - 16) * 4);
    }

    // ---------------- REG pass 2: x_mse = (yhat@rot)*n ; stash; r = xp - x_mse ----
    ull rsq2 = 0ull;
#pragma unroll
    for (int jg = 0; jg < NREG; jg += 32) {
        ull A[16];
#pragma unroll
        for (int k = 0; k < 16; ++k) A[k] = 0ull;
#pragma unroll
        for (int wi = 0; wi < 3; ++wi) {
            unsigned w = (wi == 0) ? sb0 : ((wi == 1) ? sb1 : sb2);
            const ulonglong2* mp = (const ulonglong2*)(shM + (wi * 32) * NREG + jg);
#pragma unroll 1
            for (int b = 0; b < 32; ++b) {
                ull yh2 = ((w >> b) & 1u) ? cR1p : cR0p;
#pragma unroll
                for (int t = 0; t < 8; ++t) {
                    ulonglong2 m = mp[t];
                    A[2 * t]     = fma2(yh2, m.x, A[2 * t]);
                    A[2 * t + 1] = fma2(yh2, m.y, A[2 * t + 1]);
                }
                mp += NREG / 4;
            }
        }
#pragma unroll
        for (int k = 0; k < 16; ++k) {
            ull xm2 = mul2(A[k], nrmp);
            float xl, xh;
            unpack2(xm2, xl, xh);
            int j = jg + 2 * k;
            orow[shOrd[j]]     = xl;          // stash x_mse (re-read by this thread)
            orow[shOrd[j + 1]] = xh;
            ull r2 = fma2(xm2, negonep, vp[jg / 2 + k]);
            vp[jg / 2 + k] = r2;
            rsq2 = fma2(r2, r2, rsq2);
        }
    }
    float rl, rh;
    unpack2(rsq2, rl, rh);
    float rn = fmaxf(sqrtf(rl + rh), 1e-10f);

    // reload shM with S_reg
    __syncthreads();
    for (int i = threadIdx.x; i < NREG * NREG; i += TPB) shM[i] = SR[i];
    __syncthreads();

    // ---------------- REG pass 3: sign(S @ r) ----------------
    unsigned gb0 = 0u, gb1 = 0u, gb2 = 0u;
#pragma unroll 1
    for (int ig = 0; ig < 24; ++ig) {
        const ulonglong2* r0 = (const ulonglong2*)(shM + (4 * ig + 0) * NREG);
        const ulonglong2* r1 = (const ulonglong2*)(shM + (4 * ig + 1) * NREG);
        const ulonglong2* r2 = (const ulonglong2*)(shM + (4 * ig + 2) * NREG);
        const ulonglong2* r3 = (const ulonglong2*)(shM + (4 * ig + 3) * NREG);
        ull a0 = 0ull, a1 = 0ull, a2 = 0ull, a3 = 0ull;
#pragma unroll
        for (int q = 0; q < 24; ++q) {
            ull v0 = vp[2 * q], v1 = vp[2 * q + 1];
            ulonglong2 m0 = r0[q]; a0 = fma2(m0.x, v0, a0); a0 = fma2(m0.y, v1, a0);
            ulonglong2 m1 = r1[q]; a1 = fma2(m1.x, v0, a1); a1 = fma2(m1.y, v1, a1);
            ulonglong2 m2 = r2[q]; a2 = fma2(m2.x, v0, a2); a2 = fma2(m2.y, v1, a2);
            ulonglong2 m3 = r3[q]; a3 = fma2(m3.x, v0, a3); a3 = fma2(m3.y, v1, a3);
        }
        float l0, h0, l1, h1, l2, h2, l3, h3;
        unpack2(a0, l0, h0); unpack2(a1, l1, h1);
        unpack2(a2, l2, h2); unpack2(a3, l3, h3);
        unsigned b =  (unsigned)((l0 + h0) >= 0.f)
                   | ((unsigned)((l1 + h1) >= 0.f) << 1)
                   | ((unsigned)((l2 + h2) >= 0.f) << 2)
                   | ((unsigned)((l3 + h3) >= 0.f) << 3);
        if      (ig < 8)  gb0 |= b << (ig * 4);
        else if (ig < 16) gb1 |= b << ((ig - 8) * 4);
        else              gb2 |= b << ((ig - 16) * 4);
    }

    // ---------------- REG pass 4: out = x_mse + scale*(signs@S)*rn ----------------
    {
        float cc = SCALE_R * rn;
        const ull ccp = pack2(cc, cc);
#pragma unroll
        for (int jg = 0; jg < NREG; jg += 32) {
            ull A[16];
#pragma unroll
            for (int k = 0; k < 16; ++k) A[k] = 0ull;
#pragma unroll
            for (int wi = 0; wi < 3; ++wi) {
                unsigned w = (wi == 0) ? gb0 : ((wi == 1) ? gb1 : gb2);
                const ulonglong2* mp = (const ulonglong2*)(shM + (wi * 32) * NREG + jg);
#pragma unroll 1
                for (int b = 0; b < 32; ++b) {
                    ull s2 = ((w >> b) & 1u) ? onep : negonep;
#pragma unroll
                    for (int t = 0; t < 8; ++t) {
                        ulonglong2 m = mp[t];
                        A[2 * t]     = fma2(s2, m.x, A[2 * t]);
                        A[2 * t + 1] = fma2(s2, m.y, A[2 * t + 1]);
                    }
                    mp += NREG / 4;
                }
            }
#pragma unroll
            for (int k = 0; k < 16; ++k) {
                int j = jg + 2 * k;
                int j0 = shOrd[j], j1 = shOrd[j + 1];
                ull xm2 = pack2(orow[j0], orow[j1]);
                ull res = fma2(ccp, A[k], xm2);
                float ol, oh;
                unpack2(res, ol, oh);
                orow[j0] = ol;
                orow[j1] = oh;
            }
        }
    }

    // =====================  OUTLIER subspace (32 dims, 2-bit)  =====================
    ull vop[NOUTC / 2];
    ull nsqo2 = 0ull;
#pragma unroll
    for (int p = 0; p < NOUTC / 2; ++p) {
        float a = __ldg(xr + shOrd[NREG + 2 * p]);
        float b = __ldg(xr + shOrd[NREG + 2 * p + 1]);
        ull t = pack2(a, b);
        vop[p] = t;
        nsqo2 = fma2(t, t, nsqo2);
    }
    {
        float ol, oh;
        unpack2(nsqo2, ol, oh);
        float nrmo = fmaxf(sqrtf(ol + oh), 1e-8f);
        float invo = 1.0f / nrmo;
        const ull nrmop = pack2(nrmo, nrmo);

        // pass 1: 2-bit codes
        unsigned code0 = 0u, code1 = 0u;
#pragma unroll 1
        for (int ig = 0; ig < 8; ++ig) {
            const ulonglong2* r0 = (const ulonglong2*)(shRo + (4 * ig + 0) * NOUTC);
            const ulonglong2* r1 = (const ulonglong2*)(shRo + (4 * ig + 1) * NOUTC);
            const ulonglong2* r2 = (const ulonglong2*)(shRo + (4 * ig + 2) * NOUTC);
            const ulonglong2* r3 = (const ulonglong2*)(shRo + (4 * ig + 3) * NOUTC);
            ull a0 = 0ull, a1 = 0ull, a2 = 0ull, a3 = 0ull;
#pragma unroll
            for (int q = 0; q < 8; ++q) {
                ull v0 = vop[2 * q], v1 = vop[2 * q + 1];
                ulonglong2 m0 = r0[q]; a0 = fma2(m0.x, v0, a0); a0 = fma2(m0.y, v1, a0);
                ulonglong2 m1 = r1[q]; a1 = fma2(m1.x, v0, a1); a1 = fma2(m1.y, v1, a1);
                ulonglong2 m2 = r2[q]; a2 = fma2(m2.x, v0, a2); a2 = fma2(m2.y, v1, a2);
                ulonglong2 m3 = r3[q]; a3 = fma2(m3.x, v0, a3); a3 = fma2(m3.y, v1, a3);
            }
            float l0, h0, l1, h1, l2, h2, l3, h3;
            unpack2(a0, l0, h0); unpack2(a1, l1, h1);
            unpack2(a2, l2, h2); unpack2(a3, l3, h3);
            float y0 = (l0 + h0) * invo, y1 = (l1 + h1) * invo;
            float y2 = (l2 + h2) * invo, y3 = (l3 + h3) * invo;
            unsigned i0 = (unsigned)(y0 > mO0) + (unsigned)(y0 > mO1) + (unsigned)(y0 > mO2);
            unsigned i1 = (unsigned)(y1 > mO0) + (unsigned)(y1 > mO1) + (unsigned)(y1 > mO2);
            unsigned i2 = (unsigned)(y2 > mO0) + (unsigned)(y2 > mO1) + (unsigned)(y2 > mO2);
            unsigned i3 = (unsigned)(y3 > mO0) + (unsigned)(y3 > mO1) + (unsigned)(y3 > mO2);
            unsigned b8 = i0 | (i1 << 2) | (i2 << 4) | (i3 << 6);
            if (ig < 4) code0 |= b8 << (ig * 8);
            else        code1 |= b8 << ((ig - 4) * 8);
        }

        // pass 2: x_mse (regs), r in vop
        ull xmo2[NOUTC / 2];
        ull rsqo2 = 0ull;
        {
            ull A[16];
#pragma unroll
            for (int k = 0; k < 16; ++k) A[k] = 0ull;
#pragma unroll
            for (int wi = 0; wi < 2; ++wi) {
                unsigned w = (wi == 0) ? code0 : code1;
                const ulonglong2* mp = (const ulonglong2*)(shRo + (wi * 16) * NOUTC);
#pragma unroll 1
                for (int b = 0; b < 16; ++b) {
                    unsigned idx = (w >> (2 * b)) & 3u;
                    float lo = (idx & 1u) ? cO1 : cO0;
                    float hi = (idx & 1u) ? cO3 : cO2;
                    float yh = (idx & 2u) ? hi : lo;
                    ull yh2 = pack2(yh, yh);
#pragma unroll
                    for (int t = 0; t < 8; ++t) {
                        ulonglong2 m = mp[t];
                        A[2 * t]     = fma2(yh2, m.x, A[2 * t]);
                        A[2 * t + 1] = fma2(yh2, m.y, A[2 * t + 1]);
                    }
                    mp += NOUTC / 4;
                }
            }
#pragma unroll
            for (int k = 0; k < 16; ++k) {
                ull xm2 = mul2(A[k], nrmop);
                xmo2[k] = xm2;
                ull r2 = fma2(xm2, negonep, vop[k]);
                vop[k] = r2;
                rsqo2 = fma2(r2, r2, rsqo2);
            }
        }
        float sl, sh;
        unpack2(rsqo2, sl, sh);
        float rno = fmaxf(sqrtf(sl + sh), 1e-10f);

        // pass 3: sign(S_out @ r)
        unsigned gbo = 0u;
#pragma unroll 1
        for (int ig = 0; ig < 8; ++ig) {
            const ulonglong2* r0 = (const ulonglong2*)(shSo + (4 * ig + 0) * NOUTC);
            const ulonglong2* r1 = (const ulonglong2*)(shSo + (4 * ig + 1) * NOUTC);
            const ulonglong2* r2 = (const ulonglong2*)(shSo + (4 * ig + 2) * NOUTC);
            const ulonglong2* r3 = (const ulonglong2*)(shSo + (4 * ig + 3) * NOUTC);
            ull a0 = 0ull, a1 = 0ull, a2 = 0ull, a3 = 0ull;
#pragma unroll
            for (int q = 0; q < 8; ++q) {
                ull v0 = vop[2 * q], v1 = vop[2 * q + 1];
                ulonglong2 m0 = r0[q]; a0 = fma2(m0.x, v0, a0); a0 = fma2(m0.y, v1, a0);
                ulonglong2 m1 = r1[q]; a1 = fma2(m1.x, v0, a1); a1 = fma2(m1.y, v1, a1);
                ulonglong2 m2 = r2[q]; a2 = fma2(m2.x, v0, a2); a2 = fma2(m2.y, v1, a2);
                ulonglong2 m3 = r3[q]; a3 = fma2(m3.x, v0, a3); a3 = fma2(m3.y, v1, a3);
            }
            float l0, h0, l1, h1, l2, h2, l3, h3;
            unpack2(a0, l0, h0); unpack2(a1, l1, h1);
            unpack2(a2, l2, h2); unpack2(a3, l3, h3);
            unsigned b =  (unsigned)((l0 + h0) >= 0.f)
                       | ((unsigned)((l1 + h1) >= 0.f) << 1)
                       | ((unsigned)((l2 + h2) >= 0.f) << 2)
                       | ((unsigned)((l3 + h3) >= 0.f) << 3);
            gbo |= b << (ig * 4);
        }

        // pass 4: out = x_mse + scale*(signs@S_out)*rn
        {
            float cc = SCALE_O * rno;
            const ull ccp = pack2(cc, cc);
            ull A[16];
#pragma unroll
            for (int k = 0; k < 16; ++k) A[k] = 0ull;
#pragma unroll 1
            for (int b = 0; b < 32; ++b) {
                ull s2 = ((gbo >> b) & 1u) ? onep : negonep;
                const ulonglong2* mp = (const ulonglong2*)(shSo + b * NOUTC);
#pragma unroll
                for (int t = 0; t < 8; ++t) {
                    ulonglong2 m = mp[t];
                    A[2 * t]     = fma2(s2, m.x, A[2 * t]);
                    A[2 * t + 1] = fma2(s2, m.y, A[2 * t + 1]);
                }
            }
#pragma unroll
            for (int k = 0; k < 16; ++k) {
                ull res = fma2(ccp, A[k], xmo2[k]);
                float ol, oh;
                unpack2(res, ol, oh);
                orow[shOrd[NREG + 2 * k]]     = ol;
                orow[shOrd[NREG + 2 * k + 1]] = oh;
            }
        }
    }
}

// ---------------------------------------------------------------------------
extern "C" void kernel_launch(void* const* d_in, const int* in_sizes, int n_in,
                              void* d_out, int out_size)
{
    const float* x    = (const float*)d_in[0];
    const float* rotR = (const float*)d_in[1];
    const float* rotO = (const float*)d_in[2];
    const float* cbR  = (const float*)d_in[3];
    const float* cbO  = (const float*)d_in[4];
    const float* SR   = (const float*)d_in[5];
    const float* SO   = (const float*)d_in[6];
    float* out = (float*)d_out;

    dim3 gA(NCHUNK, NBH);
    k_chnorm<<<gA, DIMC>>>(x);
    k_order<<<NBH, DIMC>>>();
    dim3 gM(SLEN / TPB, NBH);
    k_main<<<gM, TPB>>>(x, rotR, rotO, cbR, cbO, SR, SO, out);
}

// round 4
// speedup vs baseline: 1.5643x; 1.4958x over previous
#include <cuda_runtime.h>
#include <math.h>

// Shapes (fixed): x = (4,8,8192,128) fp32
#define NBH     32
#define SLEN    8192
#define DIMC    128
#define NREG    96
#define NOUTC   32
#define TPB     128
#define NCHUNK  64
#define CHUNK_S 128   // SLEN / NCHUNK

#define SCR_STRIDE 129                        // conflict-free scattered access
#define SCR_FLOATS (TPB * SCR_STRIDE)         // 16512
#define OFF_M      SCR_FLOATS                 // shM: 96*96
#define OFF_RO     (OFF_M + NREG * NREG)      // shRo: 32*32
#define OFF_SO     (OFF_RO + NOUTC * NOUTC)   // shSo: 32*32
#define OFF_ORD    (OFF_SO + NOUTC * NOUTC)
#define SMEM_FLOATS (OFF_ORD + DIMC)
#define SMEM_BYTES  (SMEM_FLOATS * 4)

typedef unsigned long long ull;

// static device scratch (no runtime allocation)
__device__ float g_partial[NBH * NCHUNK * DIMC];
__device__ int   g_order[NBH * DIMC];

// ---------------------------------------------------------------------------
// packed f32x2 helpers (FFMA2 path on sm_103a)
// ---------------------------------------------------------------------------
__device__ __forceinline__ ull pack2(float lo, float hi)
{
    ull r;
    asm("mov.b64 %0, {%1, %2};" : "=l"(r) : "f"(lo), "f"(hi));
    return r;
}
__device__ __forceinline__ void unpack2(ull p, float& lo, float& hi)
{
    asm("mov.b64 {%0, %1}, %2;" : "=f"(lo), "=f"(hi) : "l"(p));
}
__device__ __forceinline__ ull fma2(ull a, ull b, ull c)
{
    ull d;
    asm("fma.rn.f32x2 %0, %1, %2, %3;" : "=l"(d) : "l"(a), "l"(b), "l"(c));
    return d;
}
__device__ __forceinline__ ull mul2(ull a, ull b)
{
    ull d;
    asm("mul.rn.f32x2 %0, %1, %2;" : "=l"(d) : "l"(a), "l"(b));
    return d;
}

// ---------------------------------------------------------------------------
// Stage A: partial channel sum-of-squares (coalesced)
// ---------------------------------------------------------------------------
__global__ void __launch_bounds__(DIMC) k_chnorm(const float* __restrict__ x)
{
    int bh = blockIdx.y, ck = blockIdx.x, c = threadIdx.x;
    const float* p = x + ((size_t)bh * SLEN + (size_t)ck * CHUNK_S) * DIMC + c;
    float acc = 0.f;
#pragma unroll 8
    for (int s = 0; s < CHUNK_S; ++s) {
        float t = p[(size_t)s * DIMC];
        acc = fmaf(t, t, acc);
    }
    g_partial[(bh * NCHUNK + ck) * DIMC + c] = acc;
}

// ---------------------------------------------------------------------------
// Stage B: reduce + top-32 membership + stable order (non-outliers first)
// ---------------------------------------------------------------------------
__global__ void __launch_bounds__(DIMC) k_order()
{
    __shared__ float nsq[DIMC];
    __shared__ int   flag[DIMC];
    int bh = blockIdx.x, c = threadIdx.x;
    float a = 0.f;
    for (int k = 0; k < NCHUNK; ++k) a += g_partial[(bh * NCHUNK + k) * DIMC + c];
    nsq[c] = a;
    __syncthreads();
    int rank = 0;
    for (int d = 0; d < DIMC; ++d) {
        float nd = nsq[d];
        rank += (nd > a) || (nd == a && d < c);   // top_k ties: lower index wins
    }
    int isout = (rank < NOUTC) ? 1 : 0;
    flag[c] = isout;
    __syncthreads();
    int pos = 0;
    for (int d = 0; d < c; ++d) pos += (flag[d] == isout);
    g_order[bh * DIMC + (isout ? (NREG + pos) : pos)] = c;
}

// ---------------------------------------------------------------------------
// Stage C: fused roundtrip, one row per thread, packed f32x2 math,
//          ALL row-scattered access via padded shared scratch.
// ---------------------------------------------------------------------------
__global__ void __launch_bounds__(TPB, 2) k_main(
    const float* __restrict__ x,
    const float* __restrict__ rotR, const float* __restrict__ rotO,
    const float* __restrict__ cbR,  const float* __restrict__ cbO,
    const float* __restrict__ SR,   const float* __restrict__ SO,
    float* __restrict__ out)
{
    extern __shared__ float sh[];
    float* scr   = sh;                 // 128 rows x 129 floats
    float* shM   = sh + OFF_M;         // rotR, later SR
    float* shRo  = sh + OFF_RO;
    float* shSo  = sh + OFF_SO;
    int*   shOrd = (int*)(sh + OFF_ORD);

    const int bh  = blockIdx.y;
    const int tid = threadIdx.x;

    const size_t blockRowBase = (size_t)bh * SLEN + (size_t)blockIdx.x * TPB;
    const float4* xv   = (const float4*)(x   + blockRowBase * DIMC);
    float4*       outv = (float4*)      (out + blockRowBase * DIMC);

    // ---- coalesced fill of scratch (x tile), matrices, order ----
#pragma unroll 4
    for (int i = tid; i < TPB * (DIMC / 4); i += TPB) {
        float4 t = xv[i];
        int row = i >> 5, c4 = (i & 31) * 4;
        float* d = scr + row * SCR_STRIDE + c4;
        d[0] = t.x; d[1] = t.y; d[2] = t.z; d[3] = t.w;
    }
    for (int i = tid; i < NREG * NREG; i += TPB) shM[i] = rotR[i];
    for (int i = tid; i < NOUTC * NOUTC; i += TPB) { shRo[i] = rotO[i]; shSo[i] = SO[i]; }
    if (tid < DIMC) shOrd[tid] = g_order[bh * DIMC + tid];
    __syncthreads();

    float* myscr = scr + tid * SCR_STRIDE;   // this thread's row (conflict-free scattered)

    const float cR0 = __ldg(cbR), cR1 = __ldg(cbR + 1);
    const float midR = 0.5f * (cR0 + cR1);
    const float cO0 = __ldg(cbO), cO1 = __ldg(cbO + 1), cO2 = __ldg(cbO + 2), cO3 = __ldg(cbO + 3);
    const float mO0 = 0.5f * (cO0 + cO1), mO1 = 0.5f * (cO1 + cO2), mO2 = 0.5f * (cO2 + cO3);
    const float SCALE_R = 1.2533141373155003f / 96.0f;   // sqrt(pi/2)/96
    const float SCALE_O = 1.2533141373155003f / 32.0f;   // sqrt(pi/2)/32

    const ull cR0p    = pack2(cR0, cR0);
    const ull cR1p    = pack2(cR1, cR1);
    const ull onep    = pack2(1.f, 1.f);
    const ull negonep = pack2(-1.f, -1.f);

    // ---------------- gather regular subspace (packed, from scratch) ----------------
    ull vp[NREG / 2];
    ull nsq2 = 0ull;
#pragma unroll
    for (int p = 0; p < NREG / 2; ++p) {
        float a = myscr[shOrd[2 * p]];
        float b = myscr[shOrd[2 * p + 1]];
        ull t = pack2(a, b);
        vp[p] = t;
        nsq2 = fma2(t, t, nsq2);
    }
    float nl, nh;
    unpack2(nsq2, nl, nh);
    float nrm = fmaxf(sqrtf(nl + nh), 1e-8f);
    float inv = 1.0f / nrm;
    const ull nrmp = pack2(nrm, nrm);

    // ---------------- REG pass 1: y = (xp/n) @ rot.T -> 1-bit codes ----------------
    unsigned sb0 = 0u, sb1 = 0u, sb2 = 0u;
#pragma unroll 1
    for (int ig = 0; ig < 24; ++ig) {
        const ulonglong2* r0 = (const ulonglong2*)(shM + (4 * ig + 0) * NREG);
        const ulonglong2* r1 = (const ulonglong2*)(shM + (4 * ig + 1) * NREG);
        const ulonglong2* r2 = (const ulonglong2*)(shM + (4 * ig + 2) * NREG);
        const ulonglong2* r3 = (const ulonglong2*)(shM + (4 * ig + 3) * NREG);
        ull a0 = 0ull, a1 = 0ull, a2 = 0ull, a3 = 0ull;
#pragma unroll
        for (int q = 0; q < 24; ++q) {
            ull v0 = vp[2 * q], v1 = vp[2 * q + 1];
            ulonglong2 m0 = r0[q]; a0 = fma2(m0.x, v0, a0); a0 = fma2(m0.y, v1, a0);
            ulonglong2 m1 = r1[q]; a1 = fma2(m1.x, v0, a1); a1 = fma2(m1.y, v1, a1);
            ulonglong2 m2 = r2[q]; a2 = fma2(m2.x, v0, a2); a2 = fma2(m2.y, v1, a2);
            ulonglong2 m3 = r3[q]; a3 = fma2(m3.x, v0, a3); a3 = fma2(m3.y, v1, a3);
        }
        float l0, h0, l1, h1, l2, h2, l3, h3;
        unpack2(a0, l0, h0); unpack2(a1, l1, h1);
        unpack2(a2, l2, h2); unpack2(a3, l3, h3);
        unsigned b =  (unsigned)((l0 + h0) * inv > midR)
                   | ((unsigned)((l1 + h1) * inv > midR) << 1)
                   | ((unsigned)((l2 + h2) * inv > midR) << 2)
                   | ((unsigned)((l3 + h3) * inv > midR) << 3);
        if      (ig < 8)  sb0 |= b << (ig * 4);
        else if (ig < 16) sb1 |= b << ((ig - 8) * 4);
        else              sb2 |= b << ((ig - 16) * 4);
    }

    // ---------------- REG pass 2: x_mse = (yhat@rot)*n ; stash in scratch ----------
    ull rsq2 = 0ull;
#pragma unroll
    for (int jg = 0; jg < NREG; jg += 32) {
        ull A[16];
#pragma unroll
        for (int k = 0; k < 16; ++k) A[k] = 0ull;
#pragma unroll
        for (int wi = 0; wi < 3; ++wi) {
            unsigned w = (wi == 0) ? sb0 : ((wi == 1) ? sb1 : sb2);
            const ulonglong2* mp = (const ulonglong2*)(shM + (wi * 32) * NREG + jg);
#pragma unroll 1
            for (int b = 0; b < 32; ++b) {
                ull yh2 = ((w >> b) & 1u) ? cR1p : cR0p;
#pragma unroll
                for (int t = 0; t < 8; ++t) {
                    ulonglong2 m = mp[t];
                    A[2 * t]     = fma2(yh2, m.x, A[2 * t]);
                    A[2 * t + 1] = fma2(yh2, m.y, A[2 * t + 1]);
                }
                mp += NREG / 4;
            }
        }
#pragma unroll
        for (int k = 0; k < 16; ++k) {
            ull xm2 = mul2(A[k], nrmp);
            float xl, xh;
            unpack2(xm2, xl, xh);
            int j = jg + 2 * k;
            myscr[shOrd[j]]     = xl;     // stash x_mse in own scratch row slot
            myscr[shOrd[j + 1]] = xh;     // (reg-subspace channels only)
            ull r2 = fma2(xm2, negonep, vp[jg / 2 + k]);
            vp[jg / 2 + k] = r2;
            rsq2 = fma2(r2, r2, rsq2);
        }
    }
    float rl, rh;
    unpack2(rsq2, rl, rh);
    float rn = fmaxf(sqrtf(rl + rh), 1e-10f);

    // reload shM with S_reg
    __syncthreads();
    for (int i = tid; i < NREG * NREG; i += TPB) shM[i] = SR[i];
    __syncthreads();

    // ---------------- REG pass 3: sign(S @ r) ----------------
    unsigned gb0 = 0u, gb1 = 0u, gb2 = 0u;
#pragma unroll 1
    for (int ig = 0; ig < 24; ++ig) {
        const ulonglong2* r0 = (const ulonglong2*)(shM + (4 * ig + 0) * NREG);
        const ulonglong2* r1 = (const ulonglong2*)(shM + (4 * ig + 1) * NREG);
        const ulonglong2* r2 = (const ulonglong2*)(shM + (4 * ig + 2) * NREG);
        const ulonglong2* r3 = (const ulonglong2*)(shM + (4 * ig + 3) * NREG);
        ull a0 = 0ull, a1 = 0ull, a2 = 0ull, a3 = 0ull;
#pragma unroll
        for (int q = 0; q < 24; ++q) {
            ull v0 = vp[2 * q], v1 = vp[2 * q + 1];
            ulonglong2 m0 = r0[q]; a0 = fma2(m0.x, v0, a0); a0 = fma2(m0.y, v1, a0);
            ulonglong2 m1 = r1[q]; a1 = fma2(m1.x, v0, a1); a1 = fma2(m1.y, v1, a1);
            ulonglong2 m2 = r2[q]; a2 = fma2(m2.x, v0, a2); a2 = fma2(m2.y, v1, a2);
            ulonglong2 m3 = r3[q]; a3 = fma2(m3.x, v0, a3); a3 = fma2(m3.y, v1, a3);
        }
        float l0, h0, l1, h1, l2, h2, l3, h3;
        unpack2(a0, l0, h0); unpack2(a1, l1, h1);
        unpack2(a2, l2, h2); unpack2(a3, l3, h3);
        unsigned b =  (unsigned)((l0 + h0) >= 0.f)
                   | ((unsigned)((l1 + h1) >= 0.f) << 1)
                   | ((unsigned)((l2 + h2) >= 0.f) << 2)
                   | ((unsigned)((l3 + h3) >= 0.f) << 3);
        if      (ig < 8)  gb0 |= b << (ig * 4);
        else if (ig < 16) gb1 |= b << ((ig - 8) * 4);
        else              gb2 |= b << ((ig - 16) * 4);
    }

    // ---------------- REG pass 4: final = x_mse + scale*(signs@S)*rn (into scratch) --
    {
        float cc = SCALE_R * rn;
        const ull ccp = pack2(cc, cc);
#pragma unroll
        for (int jg = 0; jg < NREG; jg += 32) {
            ull A[16];
#pragma unroll
            for (int k = 0; k < 16; ++k) A[k] = 0ull;
#pragma unroll
            for (int wi = 0; wi < 3; ++wi) {
                unsigned w = (wi == 0) ? gb0 : ((wi == 1) ? gb1 : gb2);
                const ulonglong2* mp = (const ulonglong2*)(shM + (wi * 32) * NREG + jg);
#pragma unroll 1
                for (int b = 0; b < 32; ++b) {
                    ull s2 = ((w >> b) & 1u) ? onep : negonep;
#pragma unroll
                    for (int t = 0; t < 8; ++t) {
                        ulonglong2 m = mp[t];
                        A[2 * t]     = fma2(s2, m.x, A[2 * t]);
                        A[2 * t + 1] = fma2(s2, m.y, A[2 * t + 1]);
                    }
                    mp += NREG / 4;
                }
            }
#pragma unroll
            for (int k = 0; k < 16; ++k) {
                int j = jg + 2 * k;
                int j0 = shOrd[j], j1 = shOrd[j + 1];
                ull xm2 = pack2(myscr[j0], myscr[j1]);
                ull res = fma2(ccp, A[k], xm2);
                float ol, oh;
                unpack2(res, ol, oh);
                myscr[j0] = ol;
                myscr[j1] = oh;
            }
        }
    }

    // =====================  OUTLIER subspace (32 dims, 2-bit)  =====================
    ull vop[NOUTC / 2];
    ull nsqo2 = 0ull;
#pragma unroll
    for (int p = 0; p < NOUTC / 2; ++p) {
        float a = myscr[shOrd[NREG + 2 * p]];   // untouched by reg stash
        float b = myscr[shOrd[NREG + 2 * p + 1]];
        ull t = pack2(a, b);
        vop[p] = t;
        nsqo2 = fma2(t, t, nsqo2);
    }
    {
        float ol, oh;
        unpack2(nsqo2, ol, oh);
        float nrmo = fmaxf(sqrtf(ol + oh), 1e-8f);
        float invo = 1.0f / nrmo;
        const ull nrmop = pack2(nrmo, nrmo);

        // pass 1: 2-bit codes
        unsigned code0 = 0u, code1 = 0u;
#pragma unroll 1
        for (int ig = 0; ig < 8; ++ig) {
            const ulonglong2* r0 = (const ulonglong2*)(shRo + (4 * ig + 0) * NOUTC);
            const ulonglong2* r1 = (const ulonglong2*)(shRo + (4 * ig + 1) * NOUTC);
            const ulonglong2* r2 = (const ulonglong2*)(shRo + (4 * ig + 2) * NOUTC);
            const ulonglong2* r3 = (const ulonglong2*)(shRo + (4 * ig + 3) * NOUTC);
            ull a0 = 0ull, a1 = 0ull, a2 = 0ull, a3 = 0ull;
#pragma unroll
            for (int q = 0; q < 8; ++q) {
                ull v0 = vop[2 * q], v1 = vop[2 * q + 1];
                ulonglong2 m0 = r0[q]; a0 = fma2(m0.x, v0, a0); a0 = fma2(m0.y, v1, a0);
                ulonglong2 m1 = r1[q]; a1 = fma2(m1.x, v0, a1); a1 = fma2(m1.y, v1, a1);
                ulonglong2 m2 = r2[q]; a2 = fma2(m2.x, v0, a2); a2 = fma2(m2.y, v1, a2);
                ulonglong2 m3 = r3[q]; a3 = fma2(m3.x, v0, a3); a3 = fma2(m3.y, v1, a3);
            }
            float l0, h0, l1, h1, l2, h2, l3, h3;
            unpack2(a0, l0, h0); unpack2(a1, l1, h1);
            unpack2(a2, l2, h2); unpack2(a3, l3, h3);
            float y0 = (l0 + h0) * invo, y1 = (l1 + h1) * invo;
            float y2 = (l2 + h2) * invo, y3 = (l3 + h3) * invo;
            unsigned i0 = (unsigned)(y0 > mO0) + (unsigned)(y0 > mO1) + (unsigned)(y0 > mO2);
            unsigned i1 = (unsigned)(y1 > mO0) + (unsigned)(y1 > mO1) + (unsigned)(y1 > mO2);
            unsigned i2 = (unsigned)(y2 > mO0) + (unsigned)(y2 > mO1) + (unsigned)(y2 > mO2);
            unsigned i3 = (unsigned)(y3 > mO0) + (unsigned)(y3 > mO1) + (unsigned)(y3 > mO2);
            unsigned b8 = i0 | (i1 << 2) | (i2 << 4) | (i3 << 6);
            if (ig < 4) code0 |= b8 << (ig * 8);
            else        code1 |= b8 << ((ig - 4) * 8);
        }

        // pass 2: x_mse (regs), r in vop
        ull xmo2[NOUTC / 2];
        ull rsqo2 = 0ull;
        {
            ull A[16];
#pragma unroll
            for (int k = 0; k < 16; ++k) A[k] = 0ull;
#pragma unroll
            for (int wi = 0; wi < 2; ++wi) {
                unsigned w = (wi == 0) ? code0 : code1;
                const ulonglong2* mp = (const ulonglong2*)(shRo + (wi * 16) * NOUTC);
#pragma unroll 1
                for (int b = 0; b < 16; ++b) {
                    unsigned idx = (w >> (2 * b)) & 3u;
                    float lo = (idx & 1u) ? cO1 : cO0;
                    float hi = (idx & 1u) ? cO3 : cO2;
                    float yh = (idx & 2u) ? hi : lo;
                    ull yh2 = pack2(yh, yh);
#pragma unroll
                    for (int t = 0; t < 8; ++t) {
                        ulonglong2 m = mp[t];
                        A[2 * t]     = fma2(yh2, m.x, A[2 * t]);
                        A[2 * t + 1] = fma2(yh2, m.y, A[2 * t + 1]);
                    }
                    mp += NOUTC / 4;
                }
            }
#pragma unroll
            for (int k = 0; k < 16; ++k) {
                ull xm2 = mul2(A[k], nrmop);
                xmo2[k] = xm2;
                ull r2 = fma2(xm2, negonep, vop[k]);
                vop[k] = r2;
                rsqo2 = fma2(r2, r2, rsqo2);
            }
        }
        float sl, shh;
        unpack2(rsqo2, sl, shh);
        float rno = fmaxf(sqrtf(sl + shh), 1e-10f);

        // pass 3: sign(S_out @ r)
        unsigned gbo = 0u;
#pragma unroll 1
        for (int ig = 0; ig < 8; ++ig) {
            const ulonglong2* r0 = (const ulonglong2*)(shSo + (4 * ig + 0) * NOUTC);
            const ulonglong2* r1 = (const ulonglong2*)(shSo + (4 * ig + 1) * NOUTC);
            const ulonglong2* r2 = (const ulonglong2*)(shSo + (4 * ig + 2) * NOUTC);
            const ulonglong2* r3 = (const ulonglong2*)(shSo + (4 * ig + 3) * NOUTC);
            ull a0 = 0ull, a1 = 0ull, a2 = 0ull, a3 = 0ull;
#pragma unroll
            for (int q = 0; q < 8; ++q) {
                ull v0 = vop[2 * q], v1 = vop[2 * q + 1];
                ulonglong2 m0 = r0[q]; a0 = fma2(m0.x, v0, a0); a0 = fma2(m0.y, v1, a0);
                ulonglong2 m1 = r1[q]; a1 = fma2(m1.x, v0, a1); a1 = fma2(m1.y, v1, a1);
                ulonglong2 m2 = r2[q]; a2 = fma2(m2.x, v0, a2); a2 = fma2(m2.y, v1, a2);
                ulonglong2 m3 = r3[q]; a3 = fma2(m3.x, v0, a3); a3 = fma2(m3.y, v1, a3);
            }
            float l0, h0, l1, h1, l2, h2, l3, h3;
            unpack2(a0, l0, h0); unpack2(a1, l1, h1);
            unpack2(a2, l2, h2); unpack2(a3, l3, h3);
            unsigned b =  (unsigned)((l0 + h0) >= 0.f)
                       | ((unsigned)((l1 + h1) >= 0.f) << 1)
                       | ((unsigned)((l2 + h2) >= 0.f) << 2)
                       | ((unsigned)((l3 + h3) >= 0.f) << 3);
            gbo |= b << (ig * 4);
        }

        // pass 4: final outlier values into scratch
        {
            float cc = SCALE_O * rno;
            const ull ccp = pack2(cc, cc);
            ull A[16];
#pragma unroll
            for (int k = 0; k < 16; ++k) A[k] = 0ull;
#pragma unroll 1
            for (int b = 0; b < 32; ++b) {
                ull s2 = ((gbo >> b) & 1u) ? onep : negonep;
                const ulonglong2* mp = (const ulonglong2*)(shSo + b * NOUTC);
#pragma unroll
                for (int t = 0; t < 8; ++t) {
                    ulonglong2 m = mp[t];
                    A[2 * t]     = fma2(s2, m.x, A[2 * t]);
                    A[2 * t + 1] = fma2(s2, m.y, A[2 * t + 1]);
                }
            }
#pragma unroll
            for (int k = 0; k < 16; ++k) {
                ull res = fma2(ccp, A[k], xmo2[k]);
                float o0, o1;
                unpack2(res, o0, o1);
                myscr[shOrd[NREG + 2 * k]]     = o0;
                myscr[shOrd[NREG + 2 * k + 1]] = o1;
            }
        }
    }

    // ---- coalesced copy-out of finished rows ----
    __syncthreads();
#pragma unroll 4
    for (int i = tid; i < TPB * (DIMC / 4); i += TPB) {
        int row = i >> 5, c4 = (i & 31) * 4;
        const float* s = scr + row * SCR_STRIDE + c4;
        outv[i] = make_float4(s[0], s[1], s[2], s[3]);
    }
}

// ---------------------------------------------------------------------------
extern "C" void kernel_launch(void* const* d_in, const int* in_sizes, int n_in,
                              void* d_out, int out_size)
{
    const float* x    = (const float*)d_in[0];
    const float* rotR = (const float*)d_in[1];
    const float* rotO = (const float*)d_in[2];
    const float* cbR  = (const float*)d_in[3];
    const float* cbO  = (const float*)d_in[4];
    const float* SR   = (const float*)d_in[5];
    const float* SO   = (const float*)d_in[6];
    float* out = (float*)d_out;

    static int smem_set = 0;
    if (!smem_set) {
        cudaFuncSetAttribute(k_main, cudaFuncAttributeMaxDynamicSharedMemorySize, SMEM_BYTES);
        smem_set = 1;
    }

    dim3 gA(NCHUNK, NBH);
    k_chnorm<<<gA, DIMC>>>(x);
    k_order<<<NBH, DIMC>>>();
    dim3 gM(SLEN / TPB, NBH);
    k_main<<<gM, TPB, SMEM_BYTES>>>(x, rotR, rotO, cbR, cbO, SR, SO, out);
}

// round 5
// speedup vs baseline: 1.5849x; 1.0132x over previous
#include <cuda_runtime.h>
#include <math.h>

// Shapes (fixed): x = (4,8,8192,128) fp32
#define NBH     32
#define SLEN    8192
#define DIMC    128
#define NREG    96
#define NOUTC   32
#define TPB     128
#define NCHUNK  64
#define CHUNK_S 128   // SLEN / NCHUNK

#define SCR_STRIDE 129                        // conflict-free scattered access
#define SCR_FLOATS (TPB * SCR_STRIDE)         // 16512
#define OFF_M      SCR_FLOATS                 // shM: 96*96
#define OFF_RO     (OFF_M + NREG * NREG)      // shRo: 32*32
#define OFF_SO     (OFF_RO + NOUTC * NOUTC)   // shSo: 32*32
#define OFF_ORD    (OFF_SO + NOUTC * NOUTC)
#define SMEM_FLOATS (OFF_ORD + DIMC)
#define SMEM_BYTES  (SMEM_FLOATS * 4)

typedef unsigned long long ull;

// static device scratch (no runtime allocation)
__device__ float g_partial[NBH * NCHUNK * DIMC];
__device__ int   g_order[NBH * DIMC];

// ---------------------------------------------------------------------------
// packed f32x2 helpers (FFMA2 path on sm_103a)
// ---------------------------------------------------------------------------
__device__ __forceinline__ ull pack2(float lo, float hi)
{
    ull r;
    asm("mov.b64 %0, {%1, %2};" : "=l"(r) : "f"(lo), "f"(hi));
    return r;
}
__device__ __forceinline__ void unpack2(ull p, float& lo, float& hi)
{
    asm("mov.b64 {%0, %1}, %2;" : "=f"(lo), "=f"(hi) : "l"(p));
}
__device__ __forceinline__ ull fma2(ull a, ull b, ull c)
{
    ull d;
    asm("fma.rn.f32x2 %0, %1, %2, %3;" : "=l"(d) : "l"(a), "l"(b), "l"(c));
    return d;
}
__device__ __forceinline__ ull mul2(ull a, ull b)
{
    ull d;
    asm("mul.rn.f32x2 %0, %1, %2;" : "=l"(d) : "l"(a), "l"(b));
    return d;
}

// ---------------------------------------------------------------------------
// Stage A: partial channel sum-of-squares (coalesced)
// ---------------------------------------------------------------------------
__global__ void __launch_bounds__(DIMC) k_chnorm(const float* __restrict__ x)
{
    int bh = blockIdx.y, ck = blockIdx.x, c = threadIdx.x;
    const float* p = x + ((size_t)bh * SLEN + (size_t)ck * CHUNK_S) * DIMC + c;
    float acc = 0.f;
#pragma unroll 8
    for (int s = 0; s < CHUNK_S; ++s) {
        float t = p[(size_t)s * DIMC];
        acc = fmaf(t, t, acc);
    }
    g_partial[(bh * NCHUNK + ck) * DIMC + c] = acc;
}

// ---------------------------------------------------------------------------
// Stage B: reduce + top-32 membership + stable order (non-outliers first)
// ---------------------------------------------------------------------------
__global__ void __launch_bounds__(DIMC) k_order()
{
    __shared__ float nsq[DIMC];
    __shared__ int   flag[DIMC];
    int bh = blockIdx.x, c = threadIdx.x;
    float a = 0.f;
    for (int k = 0; k < NCHUNK; ++k) a += g_partial[(bh * NCHUNK + k) * DIMC + c];
    nsq[c] = a;
    __syncthreads();
    int rank = 0;
    for (int d = 0; d < DIMC; ++d) {
        float nd = nsq[d];
        rank += (nd > a) || (nd == a && d < c);   // top_k ties: lower index wins
    }
    int isout = (rank < NOUTC) ? 1 : 0;
    flag[c] = isout;
    __syncthreads();
    int pos = 0;
    for (int d = 0; d < c; ++d) pos += (flag[d] == isout);
    g_order[bh * DIMC + (isout ? (NREG + pos) : pos)] = c;
}

// ---------------------------------------------------------------------------
// Stage C: fused roundtrip, one row per thread, packed f32x2 math,
//          scattered access via padded shared scratch; b-loops unrolled x4.
// ---------------------------------------------------------------------------
__global__ void __launch_bounds__(TPB, 2) k_main(
    const float* __restrict__ x,
    const float* __restrict__ rotR, const float* __restrict__ rotO,
    const float* __restrict__ cbR,  const float* __restrict__ cbO,
    const float* __restrict__ SR,   const float* __restrict__ SO,
    float* __restrict__ out)
{
    extern __shared__ float sh[];
    float* scr   = sh;                 // 128 rows x 129 floats
    float* shM   = sh + OFF_M;         // rotR, later SR
    float* shRo  = sh + OFF_RO;
    float* shSo  = sh + OFF_SO;
    int*   shOrd = (int*)(sh + OFF_ORD);

    const int bh  = blockIdx.y;
    const int tid = threadIdx.x;

    const size_t blockRowBase = (size_t)bh * SLEN + (size_t)blockIdx.x * TPB;
    const float4* xv   = (const float4*)(x   + blockRowBase * DIMC);
    float4*       outv = (float4*)      (out + blockRowBase * DIMC);

    // ---- coalesced fill of scratch (x tile), matrices, order ----
#pragma unroll 4
    for (int i = tid; i < TPB * (DIMC / 4); i += TPB) {
        float4 t = xv[i];
        int row = i >> 5, c4 = (i & 31) * 4;
        float* d = scr + row * SCR_STRIDE + c4;
        d[0] = t.x; d[1] = t.y; d[2] = t.z; d[3] = t.w;
    }
    for (int i = tid; i < NREG * NREG; i += TPB) shM[i] = rotR[i];
    for (int i = tid; i < NOUTC * NOUTC; i += TPB) { shRo[i] = rotO[i]; shSo[i] = SO[i]; }
    if (tid < DIMC) shOrd[tid] = g_order[bh * DIMC + tid];
    __syncthreads();

    float* myscr = scr + tid * SCR_STRIDE;   // this thread's row (conflict-free scattered)

    const float cR0 = __ldg(cbR), cR1 = __ldg(cbR + 1);
    const float midR = 0.5f * (cR0 + cR1);
    const float cO0 = __ldg(cbO), cO1 = __ldg(cbO + 1), cO2 = __ldg(cbO + 2), cO3 = __ldg(cbO + 3);
    const float mO0 = 0.5f * (cO0 + cO1), mO1 = 0.5f * (cO1 + cO2), mO2 = 0.5f * (cO2 + cO3);
    const float SCALE_R = 1.2533141373155003f / 96.0f;   // sqrt(pi/2)/96
    const float SCALE_O = 1.2533141373155003f / 32.0f;   // sqrt(pi/2)/32

    const ull cR0p    = pack2(cR0, cR0);
    const ull cR1p    = pack2(cR1, cR1);
    const ull onep    = pack2(1.f, 1.f);
    const ull negonep = pack2(-1.f, -1.f);

    // ---------------- gather regular subspace (packed, from scratch) ----------------
    ull vp[NREG / 2];
    ull nsq2 = 0ull;
#pragma unroll
    for (int p = 0; p < NREG / 2; ++p) {
        float a = myscr[shOrd[2 * p]];
        float b = myscr[shOrd[2 * p + 1]];
        ull t = pack2(a, b);
        vp[p] = t;
        nsq2 = fma2(t, t, nsq2);
    }
    float nl, nh;
    unpack2(nsq2, nl, nh);
    float nrm = fmaxf(sqrtf(nl + nh), 1e-8f);
    float inv = 1.0f / nrm;
    const ull nrmp = pack2(nrm, nrm);

    // ---------------- REG pass 1: y = (xp/n) @ rot.T -> 1-bit codes ----------------
    unsigned sb0 = 0u, sb1 = 0u, sb2 = 0u;
#pragma unroll 1
    for (int ig = 0; ig < 24; ++ig) {
        const ulonglong2* r0 = (const ulonglong2*)(shM + (4 * ig + 0) * NREG);
        const ulonglong2* r1 = (const ulonglong2*)(shM + (4 * ig + 1) * NREG);
        const ulonglong2* r2 = (const ulonglong2*)(shM + (4 * ig + 2) * NREG);
        const ulonglong2* r3 = (const ulonglong2*)(shM + (4 * ig + 3) * NREG);
        ull a0 = 0ull, a1 = 0ull, a2 = 0ull, a3 = 0ull;
#pragma unroll
        for (int q = 0; q < 24; ++q) {
            ull v0 = vp[2 * q], v1 = vp[2 * q + 1];
            ulonglong2 m0 = r0[q]; a0 = fma2(m0.x, v0, a0); a0 = fma2(m0.y, v1, a0);
            ulonglong2 m1 = r1[q]; a1 = fma2(m1.x, v0, a1); a1 = fma2(m1.y, v1, a1);
            ulonglong2 m2 = r2[q]; a2 = fma2(m2.x, v0, a2); a2 = fma2(m2.y, v1, a2);
            ulonglong2 m3 = r3[q]; a3 = fma2(m3.x, v0, a3); a3 = fma2(m3.y, v1, a3);
        }
        float l0, h0, l1, h1, l2, h2, l3, h3;
        unpack2(a0, l0, h0); unpack2(a1, l1, h1);
        unpack2(a2, l2, h2); unpack2(a3, l3, h3);
        unsigned b =  (unsigned)((l0 + h0) * inv > midR)
                   | ((unsigned)((l1 + h1) * inv > midR) << 1)
                   | ((unsigned)((l2 + h2) * inv > midR) << 2)
                   | ((unsigned)((l3 + h3) * inv > midR) << 3);
        if      (ig < 8)  sb0 |= b << (ig * 4);
        else if (ig < 16) sb1 |= b << ((ig - 8) * 4);
        else              sb2 |= b << ((ig - 16) * 4);
    }

    // ---------------- REG pass 2: x_mse = (yhat@rot)*n ; stash in scratch ----------
    ull rsq2 = 0ull;
#pragma unroll
    for (int jg = 0; jg < NREG; jg += 32) {
        ull A[16];
#pragma unroll
        for (int k = 0; k < 16; ++k) A[k] = 0ull;
#pragma unroll
        for (int wi = 0; wi < 3; ++wi) {
            unsigned w = (wi == 0) ? sb0 : ((wi == 1) ? sb1 : sb2);
            const ulonglong2* mp = (const ulonglong2*)(shM + (wi * 32) * NREG + jg);
#pragma unroll 4
            for (int b = 0; b < 32; ++b) {
                ull yh2 = ((w >> b) & 1u) ? cR1p : cR0p;
#pragma unroll
                for (int t = 0; t < 8; ++t) {
                    ulonglong2 m = mp[t];
                    A[2 * t]     = fma2(yh2, m.x, A[2 * t]);
                    A[2 * t + 1] = fma2(yh2, m.y, A[2 * t + 1]);
                }
                mp += NREG / 4;
            }
        }
#pragma unroll
        for (int k = 0; k < 16; ++k) {
            ull xm2 = mul2(A[k], nrmp);
            float xl, xh;
            unpack2(xm2, xl, xh);
            int j = jg + 2 * k;
            myscr[shOrd[j]]     = xl;     // stash x_mse in own scratch row slot
            myscr[shOrd[j + 1]] = xh;     // (reg-subspace channels only)
            ull r2 = fma2(xm2, negonep, vp[jg / 2 + k]);
            vp[jg / 2 + k] = r2;
            rsq2 = fma2(r2, r2, rsq2);
        }
    }
    float rl, rh;
    unpack2(rsq2, rl, rh);
    float rn = fmaxf(sqrtf(rl + rh), 1e-10f);

    // reload shM with S_reg
    __syncthreads();
    for (int i = tid; i < NREG * NREG; i += TPB) shM[i] = SR[i];
    __syncthreads();

    // ---------------- REG pass 3: sign(S @ r) ----------------
    unsigned gb0 = 0u, gb1 = 0u, gb2 = 0u;
#pragma unroll 1
    for (int ig = 0; ig < 24; ++ig) {
        const ulonglong2* r0 = (const ulonglong2*)(shM + (4 * ig + 0) * NREG);
        const ulonglong2* r1 = (const ulonglong2*)(shM + (4 * ig + 1) * NREG);
        const ulonglong2* r2 = (const ulonglong2*)(shM + (4 * ig + 2) * NREG);
        const ulonglong2* r3 = (const ulonglong2*)(shM + (4 * ig + 3) * NREG);
        ull a0 = 0ull, a1 = 0ull, a2 = 0ull, a3 = 0ull;
#pragma unroll
        for (int q = 0; q < 24; ++q) {
            ull v0 = vp[2 * q], v1 = vp[2 * q + 1];
            ulonglong2 m0 = r0[q]; a0 = fma2(m0.x, v0, a0); a0 = fma2(m0.y, v1, a0);
            ulonglong2 m1 = r1[q]; a1 = fma2(m1.x, v0, a1); a1 = fma2(m1.y, v1, a1);
            ulonglong2 m2 = r2[q]; a2 = fma2(m2.x, v0, a2); a2 = fma2(m2.y, v1, a2);
            ulonglong2 m3 = r3[q]; a3 = fma2(m3.x, v0, a3); a3 = fma2(m3.y, v1, a3);
        }
        float l0, h0, l1, h1, l2, h2, l3, h3;
        unpack2(a0, l0, h0); unpack2(a1, l1, h1);
        unpack2(a2, l2, h2); unpack2(a3, l3, h3);
        unsigned b =  (unsigned)((l0 + h0) >= 0.f)
                   | ((unsigned)((l1 + h1) >= 0.f) << 1)
                   | ((unsigned)((l2 + h2) >= 0.f) << 2)
                   | ((unsigned)((l3 + h3) >= 0.f) << 3);
        if      (ig < 8)  gb0 |= b << (ig * 4);
        else if (ig < 16) gb1 |= b << ((ig - 8) * 4);
        else              gb2 |= b << ((ig - 16) * 4);
    }

    // ---------------- REG pass 4: final = x_mse + scale*(signs@S)*rn (into scratch) --
    {
        float cc = SCALE_R * rn;
        const ull ccp = pack2(cc, cc);
#pragma unroll
        for (int jg = 0; jg < NREG; jg += 32) {
            ull A[16];
#pragma unroll
            for (int k = 0; k < 16; ++k) A[k] = 0ull;
#pragma unroll
            for (int wi = 0; wi < 3; ++wi) {
                unsigned w = (wi == 0) ? gb0 : ((wi == 1) ? gb1 : gb2);
                const ulonglong2* mp = (const ulonglong2*)(shM + (wi * 32) * NREG + jg);
#pragma unroll 4
                for (int b = 0; b < 32; ++b) {
                    ull s2 = ((w >> b) & 1u) ? onep : negonep;
#pragma unroll
                    for (int t = 0; t < 8; ++t) {
                        ulonglong2 m = mp[t];
                        A[2 * t]     = fma2(s2, m.x, A[2 * t]);
                        A[2 * t + 1] = fma2(s2, m.y, A[2 * t + 1]);
                    }
                    mp += NREG / 4;
                }
            }
#pragma unroll
            for (int k = 0; k < 16; ++k) {
                int j = jg + 2 * k;
                int j0 = shOrd[j], j1 = shOrd[j + 1];
                ull xm2 = pack2(myscr[j0], myscr[j1]);
                ull res = fma2(ccp, A[k], xm2);
                float ol, oh;
                unpack2(res, ol, oh);
                myscr[j0] = ol;
                myscr[j1] = oh;
            }
        }
    }

    // =====================  OUTLIER subspace (32 dims, 2-bit)  =====================
    ull vop[NOUTC / 2];
    ull nsqo2 = 0ull;
#pragma unroll
    for (int p = 0; p < NOUTC / 2; ++p) {
        float a = myscr[shOrd[NREG + 2 * p]];   // untouched by reg stash
        float b = myscr[shOrd[NREG + 2 * p + 1]];
        ull t = pack2(a, b);
        vop[p] = t;
        nsqo2 = fma2(t, t, nsqo2);
    }
    {
        float ol, oh;
        unpack2(nsqo2, ol, oh);
        float nrmo = fmaxf(sqrtf(ol + oh), 1e-8f);
        float invo = 1.0f / nrmo;
        const ull nrmop = pack2(nrmo, nrmo);

        // pass 1: 2-bit codes
        unsigned code0 = 0u, code1 = 0u;
#pragma unroll 1
        for (int ig = 0; ig < 8; ++ig) {
            const ulonglong2* r0 = (const ulonglong2*)(shRo + (4 * ig + 0) * NOUTC);
            const ulonglong2* r1 = (const ulonglong2*)(shRo + (4 * ig + 1) * NOUTC);
            const ulonglong2* r2 = (const ulonglong2*)(shRo + (4 * ig + 2) * NOUTC);
            const ulonglong2* r3 = (const ulonglong2*)(shRo + (4 * ig + 3) * NOUTC);
            ull a0 = 0ull, a1 = 0ull, a2 = 0ull, a3 = 0ull;
#pragma unroll
            for (int q = 0; q < 8; ++q) {
                ull v0 = vop[2 * q], v1 = vop[2 * q + 1];
                ulonglong2 m0 = r0[q]; a0 = fma2(m0.x, v0, a0); a0 = fma2(m0.y, v1, a0);
                ulonglong2 m1 = r1[q]; a1 = fma2(m1.x, v0, a1); a1 = fma2(m1.y, v1, a1);
                ulonglong2 m2 = r2[q]; a2 = fma2(m2.x, v0, a2); a2 = fma2(m2.y, v1, a2);
                ulonglong2 m3 = r3[q]; a3 = fma2(m3.x, v0, a3); a3 = fma2(m3.y, v1, a3);
            }
            float l0, h0, l1, h1, l2, h2, l3, h3;
            unpack2(a0, l0, h0); unpack2(a1, l1, h1);
            unpack2(a2, l2, h2); unpack2(a3, l3, h3);
            float y0 = (l0 + h0) * invo, y1 = (l1 + h1) * invo;
            float y2 = (l2 + h2) * invo, y3 = (l3 + h3) * invo;
            unsigned i0 = (unsigned)(y0 > mO0) + (unsigned)(y0 > mO1) + (unsigned)(y0 > mO2);
            unsigned i1 = (unsigned)(y1 > mO0) + (unsigned)(y1 > mO1) + (unsigned)(y1 > mO2);
            unsigned i2 = (unsigned)(y2 > mO0) + (unsigned)(y2 > mO1) + (unsigned)(y2 > mO2);
            unsigned i3 = (unsigned)(y3 > mO0) + (unsigned)(y3 > mO1) + (unsigned)(y3 > mO2);
            unsigned b8 = i0 | (i1 << 2) | (i2 << 4) | (i3 << 6);
            if (ig < 4) code0 |= b8 << (ig * 8);
            else        code1 |= b8 << ((ig - 4) * 8);
        }

        // pass 2: x_mse (regs), r in vop
        ull xmo2[NOUTC / 2];
        ull rsqo2 = 0ull;
        {
            ull A[16];
#pragma unroll
            for (int k = 0; k < 16; ++k) A[k] = 0ull;
#pragma unroll
            for (int wi = 0; wi < 2; ++wi) {
                unsigned w = (wi == 0) ? code0 : code1;
                const ulonglong2* mp = (const ulonglong2*)(shRo + (wi * 16) * NOUTC);
#pragma unroll 4
                for (int b = 0; b < 16; ++b) {
                    unsigned idx = (w >> (2 * b)) & 3u;
                    float lo = (idx & 1u) ? cO1 : cO0;
                    float hi = (idx & 1u) ? cO3 : cO2;
                    float yh = (idx & 2u) ? hi : lo;
                    ull yh2 = pack2(yh, yh);
#pragma unroll
                    for (int t = 0; t < 8; ++t) {
                        ulonglong2 m = mp[t];
                        A[2 * t]     = fma2(yh2, m.x, A[2 * t]);
                        A[2 * t + 1] = fma2(yh2, m.y, A[2 * t + 1]);
                    }
                    mp += NOUTC / 4;
                }
            }
#pragma unroll
            for (int k = 0; k < 16; ++k) {
                ull xm2 = mul2(A[k], nrmop);
                xmo2[k] = xm2;
                ull r2 = fma2(xm2, negonep, vop[k]);
                vop[k] = r2;
                rsqo2 = fma2(r2, r2, rsqo2);
            }
        }
        float sl, shh;
        unpack2(rsqo2, sl, shh);
        float rno = fmaxf(sqrtf(sl + shh), 1e-10f);

        // pass 3: sign(S_out @ r)
        unsigned gbo = 0u;
#pragma unroll 1
        for (int ig = 0; ig < 8; ++ig) {
            const ulonglong2* r0 = (const ulonglong2*)(shSo + (4 * ig + 0) * NOUTC);
            const ulonglong2* r1 = (const ulonglong2*)(shSo + (4 * ig + 1) * NOUTC);
            const ulonglong2* r2 = (const ulonglong2*)(shSo + (4 * ig + 2) * NOUTC);
            const ulonglong2* r3 = (const ulonglong2*)(shSo + (4 * ig + 3) * NOUTC);
            ull a0 = 0ull, a1 = 0ull, a2 = 0ull, a3 = 0ull;
#pragma unroll
            for (int q = 0; q < 8; ++q) {
                ull v0 = vop[2 * q], v1 = vop[2 * q + 1];
                ulonglong2 m0 = r0[q]; a0 = fma2(m0.x, v0, a0); a0 = fma2(m0.y, v1, a0);
                ulonglong2 m1 = r1[q]; a1 = fma2(m1.x, v0, a1); a1 = fma2(m1.y, v1, a1);
                ulonglong2 m2 = r2[q]; a2 = fma2(m2.x, v0, a2); a2 = fma2(m2.y, v1, a2);
                ulonglong2 m3 = r3[q]; a3 = fma2(m3.x, v0, a3); a3 = fma2(m3.y, v1, a3);
            }
            float l0, h0, l1, h1, l2, h2, l3, h3;
            unpack2(a0, l0, h0); unpack2(a1, l1, h1);
            unpack2(a2, l2, h2); unpack2(a3, l3, h3);
            unsigned b =  (unsigned)((l0 + h0) >= 0.f)
                       | ((unsigned)((l1 + h1) >= 0.f) << 1)
                       | ((unsigned)((l2 + h2) >= 0.f) << 2)
                       | ((unsigned)((l3 + h3) >= 0.f) << 3);
            gbo |= b << (ig * 4);
        }

        // pass 4: final outlier values into scratch
        {
            float cc = SCALE_O * rno;
            const ull ccp = pack2(cc, cc);
            ull A[16];
#pragma unroll
            for (int k = 0; k < 16; ++k) A[k] = 0ull;
#pragma unroll 4
            for (int b = 0; b < 32; ++b) {
                ull s2 = ((gbo >> b) & 1u) ? onep : negonep;
                const ulonglong2* mp = (const ulonglong2*)(shSo + b * NOUTC);
#pragma unroll
                for (int t = 0; t < 8; ++t) {
                    ulonglong2 m = mp[t];
                    A[2 * t]     = fma2(s2, m.x, A[2 * t]);
                    A[2 * t + 1] = fma2(s2, m.y, A[2 * t + 1]);
                }
            }
#pragma unroll
            for (int k = 0; k < 16; ++k) {
                ull res = fma2(ccp, A[k], xmo2[k]);
                float o0, o1;
                unpack2(res, o0, o1);
                myscr[shOrd[NREG + 2 * k]]     = o0;
                myscr[shOrd[NREG + 2 * k + 1]] = o1;
            }
        }
    }

    // ---- coalesced copy-out of finished rows ----
    __syncthreads();
#pragma unroll 4
    for (int i = tid; i < TPB * (DIMC / 4); i += TPB) {
        int row = i >> 5, c4 = (i & 31) * 4;
        const float* s = scr + row * SCR_STRIDE + c4;
        outv[i] = make_float4(s[0], s[1], s[2], s[3]);
    }
}

// ---------------------------------------------------------------------------
extern "C" void kernel_launch(void* const* d_in, const int* in_sizes, int n_in,
                              void* d_out, int out_size)
{
    const float* x    = (const float*)d_in[0];
    const float* rotR = (const float*)d_in[1];
    const float* rotO = (const float*)d_in[2];
    const float* cbR  = (const float*)d_in[3];
    const float* cbO  = (const float*)d_in[4];
    const float* SR   = (const float*)d_in[5];
    const float* SO   = (const float*)d_in[6];
    float* out = (float*)d_out;

    static int smem_set = 0;
    if (!smem_set) {
        cudaFuncSetAttribute(k_main, cudaFuncAttributeMaxDynamicSharedMemorySize, SMEM_BYTES);
        smem_set = 1;
    }

    dim3 gA(NCHUNK, NBH);
    k_chnorm<<<gA, DIMC>>>(x);
    k_order<<<NBH, DIMC>>>();
    dim3 gM(SLEN / TPB, NBH);
    k_main<<<gM, TPB, SMEM_BYTES>>>(x, rotR, rotO, cbR, cbO, SR, SO, out);
}